// round 6
// baseline (speedup 1.0000x reference)
#include <cuda_runtime.h>
#include <cuda_bf16.h>
#include <cstdint>
#include <cfloat>

#define BATCH 4
#define DDIM 256
#define NSEQ 4096
#define KCB 8192
#define MTOT (BATCH * NSEQ)      // 16384 queries
#define KTOT 768                 // cat-K: [xh | xh | xl] vs [eh | el | eh]
#define NKT 12                   // 768 / 64 halves per k-tile
#define GAPTH 4e-3f
#define SMEM_BYTES 75776

// staged operands, ldmatrix-ready swizzled 128B rows, [ktile][row][128B]
__device__ uint8_t g_A[(size_t)NKT * MTOT * 128];   // 25.2 MB
__device__ uint8_t g_Bm[(size_t)NKT * KCB * 128];   // 12.6 MB
__device__ float   g_e2[KCB];
__device__ float   g_pv1[8 * MTOT];
__device__ int     g_pi1[8 * MTOT];
__device__ float   g_pv2[8 * MTOT];
__device__ int     g_codes[MTOT];
__device__ float   g_gap[MTOT];

__device__ __forceinline__ uint32_t smem_u32(const void* p) {
    uint32_t a;
    asm("{ .reg .u64 t; cvta.to.shared.u64 t, %1; cvt.u32.u64 %0, t; }" : "=r"(a) : "l"(p));
    return a;
}
__device__ __forceinline__ uint32_t pack_bf2(float a, float b) {
    __nv_bfloat162 h = __floats2bfloat162_rn(a, b);
    return *reinterpret_cast<uint32_t*>(&h);
}

#define CP_ASYNC16(s, g) asm volatile("cp.async.cg.shared.global [%0], [%1], 16;" :: "r"(s), "l"(g))
#define CP_COMMIT()      asm volatile("cp.async.commit_group;")
#define CP_WAIT1()       asm volatile("cp.async.wait_group 1;")

#define LDM_X4(r, a) \
    asm volatile("ldmatrix.sync.aligned.m8n8.x4.shared.b16 {%0,%1,%2,%3}, [%4];" \
        : "=r"((r)[0]), "=r"((r)[1]), "=r"((r)[2]), "=r"((r)[3]) : "r"(a))

#define MMA_BF16(c, a, b0, b1) \
    asm volatile("mma.sync.aligned.m16n8k16.row.col.f32.bf16.bf16.f32 " \
        "{%0,%1,%2,%3},{%4,%5,%6,%7},{%8,%9},{%0,%1,%2,%3};" \
        : "+f"((c)[0]), "+f"((c)[1]), "+f"((c)[2]), "+f"((c)[3]) \
        : "r"((a)[0]), "r"((a)[1]), "r"((a)[2]), "r"((a)[3]), "r"(b0), "r"(b1))

// ---------------- e2[k] = ||e_k||^2 (fp64 accum) ----------------
__global__ void e2_kernel(const float* __restrict__ e) {
    const int w = (blockIdx.x * blockDim.x + threadIdx.x) >> 5;
    const int lane = threadIdx.x & 31;
    double acc = 0.0;
#pragma unroll
    for (int j = 0; j < 8; j++) {
        float v = e[(size_t)w * DDIM + lane + 32 * j];
        acc += (double)v * (double)v;
    }
#pragma unroll
    for (int off = 16; off; off >>= 1) acc += __shfl_down_sync(0xffffffffu, acc, off);
    if (lane == 0) g_e2[w] = (float)acc;
}

// swizzled write position for word-column cc (bf16x2) of row `row`
__device__ __forceinline__ size_t sw_off(size_t rows_total, int row, int cc) {
    const int kt = cc >> 5;                       // k-tile
    const int unit = (cc & 31) >> 2;              // 16B unit within 128B row
    return ((size_t)kt * rows_total + row) * 128
         + (size_t)(((unit ^ (row & 7)) << 4) + ((4 * cc) & 15));
}

// ---------------- stage B: e [K,D] -> g_Bm cat [eh | el | eh] ----------------
__global__ void prep_e(const float* __restrict__ e) {
    const int t = threadIdx.x;
    const int k = blockIdx.x * 8 + (t >> 5);
    const int lane = t & 31;
    const float2* er = reinterpret_cast<const float2*>(e + (size_t)k * DDIM);
#pragma unroll
    for (int jj = 0; jj < 4; jj++) {
        int c = lane + 32 * jj;                   // d-pair index 0..127
        float2 v = er[c];
        __nv_bfloat16 h0 = __float2bfloat16_rn(v.x), h1 = __float2bfloat16_rn(v.y);
        uint32_t hi = pack_bf2(v.x, v.y);
        uint32_t lo = pack_bf2(v.x - __bfloat162float(h0), v.y - __bfloat162float(h1));
        *reinterpret_cast<uint32_t*>(g_Bm + sw_off(KCB, k, c))       = hi;
        *reinterpret_cast<uint32_t*>(g_Bm + sw_off(KCB, k, c + 128)) = lo;
        *reinterpret_cast<uint32_t*>(g_Bm + sw_off(KCB, k, c + 256)) = hi;
    }
}

// ---------------- stage A: x [B,D,N] -> g_A cat [xh | xh | xl] ----------------
__global__ void prep_x(const float* __restrict__ x) {
    __shared__ uint32_t sh[32][33];
    __shared__ uint32_t sl[32][33];
    const int blk = blockIdx.x, r0 = blockIdx.y * 32, c0 = blockIdx.z * 32;
    const int tx = threadIdx.x, ty = threadIdx.y;
    const int b = blk >> 5;
    const int nbase = (blk & 31) * 128;
#pragma unroll
    for (int j = 0; j < 4; j++) {
        int c = c0 + ty + 8 * j;                  // d-pair index
        int n = nbase + r0 + tx;
        float v0 = x[((size_t)b * DDIM + 2 * c) * NSEQ + n];
        float v1 = x[((size_t)b * DDIM + 2 * c + 1) * NSEQ + n];
        __nv_bfloat16 h0 = __float2bfloat16_rn(v0), h1 = __float2bfloat16_rn(v1);
        sh[ty + 8 * j][tx] = pack_bf2(v0, v1);
        sl[ty + 8 * j][tx] = pack_bf2(v0 - __bfloat162float(h0), v1 - __bfloat162float(h1));
    }
    __syncthreads();
#pragma unroll
    for (int j = 0; j < 4; j++) {
        int q = blk * 128 + r0 + ty + 8 * j;
        int c = c0 + tx;
        uint32_t hi = sh[tx][ty + 8 * j];
        uint32_t lo = sl[tx][ty + 8 * j];
        *reinterpret_cast<uint32_t*>(g_A + sw_off(MTOT, q, c))       = hi;
        *reinterpret_cast<uint32_t*>(g_A + sw_off(MTOT, q, c + 128)) = hi;
        *reinterpret_cast<uint32_t*>(g_A + sw_off(MTOT, q, c + 256)) = lo;
    }
}

// ---------------- main mma.sync kernel ----------------
__device__ __forceinline__ void copy_tile(int i, int buf, uint32_t sbase,
                                          int blk, int cg, int t) {
    const int kt = i % NKT, nt = i / NKT;
    const uint8_t* As = g_A + ((size_t)kt * MTOT + blk * 128) * 128;
    const uint8_t* Bs = g_Bm + ((size_t)kt * KCB + cg * 1024 + nt * 128) * 128;
    const uint32_t sA = sbase + buf * 32768u, sB = sA + 16384u;
#pragma unroll
    for (int j = 0; j < 4; j++) {
        int off = t * 16 + j * 4096;
        CP_ASYNC16(sA + off, As + off);
        CP_ASYNC16(sB + off, Bs + off);
    }
}

__device__ __forceinline__ void top2_upd(float sc, int k, float& v1, int& i1, float& v2) {
    if (sc < v1) { v2 = v1; v1 = sc; i1 = k; }
    else if (sc < v2) v2 = sc;
}

__global__ __launch_bounds__(256, 2) void vq_mma_kernel() {
    extern __shared__ uint8_t smem[];
    const uint32_t sbase = smem_u32(smem);
    const int t = threadIdx.x;
    const int lane = t & 31;
    const int w = t >> 5, wm = w >> 2, wn = w & 3;
    const int blk = blockIdx.x, cg = blockIdx.y;

    float* e2s = reinterpret_cast<float*>(smem + 65536);   // 1024 floats
    float* rv1 = reinterpret_cast<float*>(smem + 69632);   // 512
    int*   ri1 = reinterpret_cast<int*>(smem + 71680);     // 512
    float* rv2 = reinterpret_cast<float*>(smem + 73728);   // 512

    rv1[t] = FLT_MAX; rv1[t + 256] = FLT_MAX;
    rv2[t] = FLT_MAX; rv2[t + 256] = FLT_MAX;
    ri1[t] = 0x7fffffff; ri1[t + 256] = 0x7fffffff;
#pragma unroll
    for (int j = 0; j < 4; j++) e2s[t + 256 * j] = g_e2[cg * 1024 + t + 256 * j];

    // ldmatrix lane address components
    const int lrow = (lane & 7) + ((lane >> 3) & 1) * 8;   // row within 16-row tile
    const int lhalf = lane >> 4;                            // k 16B-unit parity
    uint32_t aoff[4], axr[4], boff[2], bxr[2];
#pragma unroll
    for (int mi = 0; mi < 4; mi++) {
        int row = wm * 64 + mi * 16 + lrow;
        aoff[mi] = row * 128; axr[mi] = row & 7;
    }
#pragma unroll
    for (int np = 0; np < 2; np++) {
        int row = wn * 32 + np * 16 + lrow;
        boff[np] = row * 128; bxr[np] = row & 7;
    }

    float acc[4][4][4];
#pragma unroll
    for (int mi = 0; mi < 4; mi++)
#pragma unroll
        for (int ni = 0; ni < 4; ni++)
#pragma unroll
            for (int r = 0; r < 4; r++) acc[mi][ni][r] = 0.0f;

    copy_tile(0, 0, sbase, blk, cg, t);
    CP_COMMIT();

    for (int i = 0; i < 8 * NKT; i++) {
        const int buf = i & 1;
        if (i + 1 < 8 * NKT) copy_tile(i + 1, buf ^ 1, sbase, blk, cg, t);
        CP_COMMIT();
        CP_WAIT1();
        __syncthreads();
        const uint32_t sAb = sbase + buf * 32768u, sBb = sAb + 16384u;
#pragma unroll
        for (int s = 0; s < 4; s++) {
            uint32_t af[4][4], bf[2][4];
#pragma unroll
            for (int mi = 0; mi < 4; mi++)
                LDM_X4(af[mi], sAb + aoff[mi] + ((((uint32_t)(2 * s + lhalf)) ^ axr[mi]) << 4));
#pragma unroll
            for (int np = 0; np < 2; np++)
                LDM_X4(bf[np], sBb + boff[np] + ((((uint32_t)(2 * s + lhalf)) ^ bxr[np]) << 4));
#pragma unroll
            for (int mi = 0; mi < 4; mi++)
#pragma unroll
                for (int ni = 0; ni < 4; ni++) {
                    const int np = ni >> 1, p = ni & 1;
                    MMA_BF16(acc[mi][ni], af[mi], bf[np][p], bf[np][p + 2]);
                }
        }
        if ((i % NKT) == NKT - 1) {
            const int nt = i / NKT;
            // fused top-2 argmin epilogue for this 128-code slab
#pragma unroll
            for (int mi = 0; mi < 4; mi++) {
#pragma unroll
                for (int half = 0; half < 2; half++) {
                    const int rloc = wm * 64 + mi * 16 + (lane >> 2) + half * 8;
                    float v1 = FLT_MAX, v2 = FLT_MAX; int i1 = 0x7fffffff;
#pragma unroll
                    for (int ni = 0; ni < 4; ni++) {
#pragma unroll
                        for (int jj = 0; jj < 2; jj++) {
                            int nl = wn * 32 + ni * 8 + (lane & 3) * 2 + jj;
                            float sc = fmaf(-2.0f, acc[mi][ni][half * 2 + jj],
                                            e2s[nt * 128 + nl]);
                            top2_upd(sc, cg * 1024 + nt * 128 + nl, v1, i1, v2);
                        }
                    }
#pragma unroll
                    for (int off = 1; off <= 2; off <<= 1) {
                        float ov1 = __shfl_xor_sync(0xffffffffu, v1, off);
                        int   oi1 = __shfl_xor_sync(0xffffffffu, i1, off);
                        float ov2 = __shfl_xor_sync(0xffffffffu, v2, off);
                        if (ov1 < v1 || (ov1 == v1 && oi1 < i1)) {
                            v2 = fminf(v1, ov2); v1 = ov1; i1 = oi1;
                        } else v2 = fminf(v2, ov1);
                    }
                    if ((lane & 3) == 0) {
                        const int slot = wn * 128 + rloc;
                        float cv = rv1[slot];
                        if (v1 < cv || (v1 == cv && i1 < ri1[slot])) {
                            rv2[slot] = fminf(cv, fminf(rv2[slot], v2));
                            rv1[slot] = v1; ri1[slot] = i1;
                        } else {
                            rv2[slot] = fminf(rv2[slot], v1);
                        }
                    }
                }
            }
#pragma unroll
            for (int mi = 0; mi < 4; mi++)
#pragma unroll
                for (int ni = 0; ni < 4; ni++)
#pragma unroll
                    for (int r = 0; r < 4; r++) acc[mi][ni][r] = 0.0f;
        }
        __syncthreads();
    }

    if (t < 128) {
        float v1 = rv1[t]; int i1 = ri1[t]; float v2 = rv2[t];
#pragma unroll
        for (int s = 1; s < 4; s++) {
            float ov1 = rv1[s * 128 + t]; int oi1 = ri1[s * 128 + t];
            float ov2 = rv2[s * 128 + t];
            if (ov1 < v1 || (ov1 == v1 && oi1 < i1)) {
                v2 = fminf(v1, ov2); v1 = ov1; i1 = oi1;
            } else v2 = fminf(v2, ov1);
        }
        const size_t idx = (size_t)cg * MTOT + blk * 128 + t;
        g_pv1[idx] = v1; g_pi1[idx] = i1; g_pv2[idx] = v2;
    }
}

// ---------------- reduce 8 code-group partials ----------------
__global__ void reduce2_kernel() {
    const int q = blockIdx.x * blockDim.x + threadIdx.x;
    float v1 = g_pv1[q]; int i1 = g_pi1[q]; float v2 = g_pv2[q];
#pragma unroll
    for (int s = 1; s < 8; s++) {
        const size_t idx = (size_t)s * MTOT + q;
        float ov1 = g_pv1[idx]; int oi1 = g_pi1[idx]; float ov2 = g_pv2[idx];
        if (ov1 < v1 || (ov1 == v1 && oi1 < i1)) {
            v2 = fminf(v1, ov2); v1 = ov1; i1 = oi1;
        } else v2 = fminf(v2, ov1);
    }
    g_codes[q] = i1;
    g_gap[q] = v2 - v1;
}

// ---------------- fixup: exact fp32 re-scan for near-tie queries -------------
__global__ void fixup_kernel(const float* __restrict__ x, const float* __restrict__ e) {
    const int q = blockIdx.x;
    if (g_gap[q] >= GAPTH) return;
    __shared__ float xs[DDIM];
    __shared__ float bv[256];
    __shared__ int   bi[256];
    const int t = threadIdx.x;
    const int b = q >> 12, n = q & (NSEQ - 1);
    xs[t] = x[((size_t)b * DDIM + t) * NSEQ + n];
    __syncthreads();
    float best = FLT_MAX; int bidx = 0x7fffffff;
    for (int k = t; k < KCB; k += 256) {
        const float* er = e + (size_t)k * DDIM;
        float acc = 0.0f;
#pragma unroll 8
        for (int d = 0; d < DDIM; d++) acc = fmaf(xs[d], er[d], acc);
        float sc = fmaf(-2.0f, acc, g_e2[k]);
        if (sc < best) { best = sc; bidx = k; }
    }
    bv[t] = best; bi[t] = bidx;
    __syncthreads();
    for (int s = 128; s; s >>= 1) {
        if (t < s) {
            float v = bv[t + s]; int ix = bi[t + s];
            if (v < bv[t] || (v == bv[t] && ix < bi[t])) { bv[t] = v; bi[t] = ix; }
        }
        __syncthreads();
    }
    if (t == 0) g_codes[q] = bi[0];
}

// ---------------- gather: out[b,d,n] = e[code,d] ----------------
__global__ void gather_kernel(const float* __restrict__ e, float* __restrict__ out) {
    __shared__ int   scode[32];
    __shared__ float tile[32][65];
    const int t = threadIdx.x;
    const int q0 = blockIdx.x * 32;
    const int b = q0 / NSEQ;
    const int n0 = q0 % NSEQ;
    if (t < 32) scode[t] = g_codes[q0 + t];
    __syncthreads();
    const int cl = t >> 3, dp = (t & 7) * 8;
    const int c2 = t & 31, dg = t >> 5;
    const int code = scode[cl];
    for (int ch = 0; ch < 4; ch++) {
        const int d0 = ch * 64;
        float4 v0 = *reinterpret_cast<const float4*>(&e[(size_t)code * DDIM + d0 + dp]);
        float4 v1 = *reinterpret_cast<const float4*>(&e[(size_t)code * DDIM + d0 + dp + 4]);
        tile[cl][dp+0]=v0.x; tile[cl][dp+1]=v0.y; tile[cl][dp+2]=v0.z; tile[cl][dp+3]=v0.w;
        tile[cl][dp+4]=v1.x; tile[cl][dp+5]=v1.y; tile[cl][dp+6]=v1.z; tile[cl][dp+7]=v1.w;
        __syncthreads();
#pragma unroll
        for (int dd = 0; dd < 8; dd++) {
            int d = dd * 8 + dg;
            out[((size_t)b * DDIM + d0 + d) * NSEQ + n0 + c2] = tile[c2][d];
        }
        __syncthreads();
    }
}

// ---------------------------------------------------------------------------
extern "C" void kernel_launch(void* const* d_in, const int* in_sizes, int n_in,
                              void* d_out, int out_size) {
    const float* x = (const float*)d_in[0];  // [B, D, N] fp32
    const float* e = (const float*)d_in[1];  // [K, D]    fp32
    float* out = (float*)d_out;              // [B, D, N] fp32

    cudaFuncSetAttribute(vq_mma_kernel, cudaFuncAttributeMaxDynamicSharedMemorySize, SMEM_BYTES);

    e2_kernel<<<(KCB * 32) / 256, 256>>>(e);
    prep_e<<<KCB / 8, 256>>>(e);
    prep_x<<<dim3(MTOT / 128, 4, 4), dim3(32, 8)>>>(x);
    vq_mma_kernel<<<dim3(MTOT / 128, 8), 256, SMEM_BYTES>>>();
    reduce2_kernel<<<MTOT / 256, 256>>>();
    fixup_kernel<<<MTOT, 256>>>(x, e);
    gather_kernel<<<MTOT / 32, 256>>>(e, out);
}